// round 1
// baseline (speedup 1.0000x reference)
#include <cuda_runtime.h>
#include <math.h>

// ---------------------------------------------------------------------------
// TreeLSTM: leaf projection + 12 levels of binary REDUCE.
// Shapes (derived at runtime from in_sizes): B=8, L=4096, D=300, H=128.
//
// Key layout fact: with h stored as [B, n_prev, H] contiguous, the pair
// (h_l, h_r) = (h[:,2m], h[:,2m+1]) occupies consecutive rows, so the level
// GEMM's A operand is simply the previous h buffer viewed as [B*n, 2H].
// Same for c (c_l at row offset 0..H, c_r at H..2H of the 2H-wide view).
// ---------------------------------------------------------------------------

#define Hc   128
#define MAXBL 32768           // B*L
#define NGATE 640             // 5*H

// Static scratch (allocation-free rule).
__device__ float g_hA[MAXBL * Hc];
__device__ float g_cA[MAXBL * Hc];
__device__ float g_hB[(MAXBL / 2) * Hc];
__device__ float g_cB[(MAXBL / 2) * Hc];
__device__ float g_gates[(MAXBL / 2) * NGATE];
__device__ float g_Wst[2 * Hc * NGATE];   // [W_l; W_r] stacked: [256, 640]

// ---------------------------------------------------------------------------
// Stack W_l and W_r into one [2H, 5H] matrix.
// ---------------------------------------------------------------------------
__global__ void stack_w_kernel(const float* __restrict__ Wl,
                               const float* __restrict__ Wr,
                               float* __restrict__ Wst, int elems)
{
    int idx = blockIdx.x * blockDim.x + threadIdx.x;
    if (idx < elems) {
        Wst[idx]         = Wl[idx];
        Wst[idx + elems] = Wr[idx];
    }
}

// ---------------------------------------------------------------------------
// Tiled fp32 GEMM: C = A[M,K] @ B[K,N] + bias[N], with split epilogue.
// Columns [0, splitCol) go to C0 (row stride splitCol),
// columns [splitCol, N) go to C1 (row stride N - splitCol).
// For the level GEMM pass splitCol = N (everything to C0).
// BM=BN=64, BK=16, 256 threads, 4x4 accumulators per thread.
// ---------------------------------------------------------------------------
#define BM 64
#define BN 64
#define BK 16

__global__ __launch_bounds__(256)
void gemm_bias_split(const float* __restrict__ A,
                     const float* __restrict__ B,
                     const float* __restrict__ bias,
                     float* __restrict__ C0,
                     float* __restrict__ C1,
                     int M, int N, int K, int splitCol)
{
    __shared__ float As[BM][BK + 1];             // +1 pad: conflict-free column reads
    __shared__ __align__(16) float Bs[BK][BN];

    const int bm  = blockIdx.x * BM;
    const int bn  = blockIdx.y * BN;
    const int tid = threadIdx.x;       // 0..255
    const int tx  = tid & 15;          // N-direction
    const int ty  = tid >> 4;          // M-direction

    float acc[4][4] = {};

    for (int k0 = 0; k0 < K; k0 += BK) {
        // Load A tile (64x16): 4 elems/thread, kk fastest -> coalesced-ish.
        #pragma unroll
        for (int i = 0; i < 4; i++) {
            int e  = tid + i * 256;
            int m  = e >> 4;
            int kk = e & 15;
            float v = 0.f;
            if (bm + m < M && k0 + kk < K)
                v = A[(size_t)(bm + m) * K + (k0 + kk)];
            As[m][kk] = v;
        }
        // Load B tile (16x64): 4 elems/thread, j fastest -> coalesced.
        #pragma unroll
        for (int i = 0; i < 4; i++) {
            int e  = tid + i * 256;
            int kk = e >> 6;
            int j  = e & 63;
            float v = 0.f;
            if (k0 + kk < K && bn + j < N)
                v = B[(size_t)(k0 + kk) * N + (bn + j)];
            Bs[kk][j] = v;
        }
        __syncthreads();

        #pragma unroll
        for (int kk = 0; kk < BK; kk++) {
            float a0 = As[ty * 4 + 0][kk];
            float a1 = As[ty * 4 + 1][kk];
            float a2 = As[ty * 4 + 2][kk];
            float a3 = As[ty * 4 + 3][kk];
            float4 bv = *(const float4*)&Bs[kk][tx * 4];
            acc[0][0] += a0 * bv.x; acc[0][1] += a0 * bv.y; acc[0][2] += a0 * bv.z; acc[0][3] += a0 * bv.w;
            acc[1][0] += a1 * bv.x; acc[1][1] += a1 * bv.y; acc[1][2] += a1 * bv.z; acc[1][3] += a1 * bv.w;
            acc[2][0] += a2 * bv.x; acc[2][1] += a2 * bv.y; acc[2][2] += a2 * bv.z; acc[2][3] += a2 * bv.w;
            acc[3][0] += a3 * bv.x; acc[3][1] += a3 * bv.y; acc[3][2] += a3 * bv.z; acc[3][3] += a3 * bv.w;
        }
        __syncthreads();
    }

    // Epilogue with bias + split routing.
    #pragma unroll
    for (int i = 0; i < 4; i++) {
        int row = bm + ty * 4 + i;
        if (row >= M) continue;
        #pragma unroll
        for (int j = 0; j < 4; j++) {
            int col = bn + tx * 4 + j;
            if (col >= N) continue;
            float v = acc[i][j] + bias[col];
            if (col < splitCol)
                C0[(size_t)row * splitCol + col] = v;
            else
                C1[(size_t)row * (N - splitCol) + (col - splitCol)] = v;
        }
    }
}

// ---------------------------------------------------------------------------
// LSTM cell: gates[M, 640] + c_prev (viewed [M, 256]: c_l | c_r) -> h, c [M,128]
// ---------------------------------------------------------------------------
__device__ __forceinline__ float sigmoidf_(float x) {
    return 1.0f / (1.0f + expf(-x));
}

__global__ void lstm_cell_kernel(const float* __restrict__ gates,
                                 const float* __restrict__ c_prev,
                                 float* __restrict__ h_out,
                                 float* __restrict__ c_out,
                                 int M)
{
    int idx = blockIdx.x * blockDim.x + threadIdx.x;
    if (idx >= M * Hc) return;
    int r = idx >> 7;          // /128
    int j = idx & 127;

    const float* g = gates + (size_t)r * NGATE;
    float gi = sigmoidf_(g[j]);
    float fl = sigmoidf_(g[Hc + j]);
    float fr = sigmoidf_(g[2 * Hc + j]);
    float go = sigmoidf_(g[3 * Hc + j]);
    float gg = tanhf(g[4 * Hc + j]);

    float cl = c_prev[(size_t)r * (2 * Hc) + j];
    float cr = c_prev[(size_t)r * (2 * Hc) + Hc + j];

    float c = fl * cl + fr * cr + gi * gg;
    c_out[idx] = c;
    h_out[idx] = go * tanhf(c);
}

// ---------------------------------------------------------------------------
// Launch
// ---------------------------------------------------------------------------
extern "C" void kernel_launch(void* const* d_in, const int* in_sizes, int n_in,
                              void* d_out, int out_size)
{
    const float* x      = (const float*)d_in[0];
    const float* W_leaf = (const float*)d_in[1];
    const float* b_leaf = (const float*)d_in[2];
    const float* W_l    = (const float*)d_in[3];
    const float* W_r    = (const float*)d_in[4];
    const float* bg     = (const float*)d_in[5];

    const int twoH = in_sizes[2];            // 256
    const int H    = twoH / 2;               // 128
    const int D    = in_sizes[1] / twoH;     // 300
    const int BL   = in_sizes[0] / D;        // 32768
    const int B    = out_size / H;           // 8
    const int L    = BL / B;                 // 4096
    int levels = 0;
    for (int t = L; t > 1; t >>= 1) levels++;

    float *hA, *cA, *hB, *cB, *gates, *Wst;
    cudaGetSymbolAddress((void**)&hA,    g_hA);
    cudaGetSymbolAddress((void**)&cA,    g_cA);
    cudaGetSymbolAddress((void**)&hB,    g_hB);
    cudaGetSymbolAddress((void**)&cB,    g_cB);
    cudaGetSymbolAddress((void**)&gates, g_gates);
    cudaGetSymbolAddress((void**)&Wst,   g_Wst);

    // 1) Stack [W_l; W_r] -> Wst [2H, 5H]
    {
        int elems = H * 5 * H;
        stack_w_kernel<<<(elems + 255) / 256, 256>>>(W_l, W_r, Wst, elems);
    }

    // 2) Leaf GEMM: hc = x @ W_leaf + b_leaf, split into hA (cols<H) / cA.
    {
        dim3 grid((BL + BM - 1) / BM, (twoH + BN - 1) / BN);
        gemm_bias_split<<<grid, 256>>>(x, W_leaf, b_leaf, hA, cA,
                                       BL, twoH, D, H);
    }

    // 3) Reduction levels (ping-pong A <-> B).
    float* src_h = hA; float* src_c = cA;
    float* dst_h = hB; float* dst_c = cB;
    int n = L;
    for (int lvl = 0; lvl < levels; lvl++) {
        n >>= 1;                 // pairs at this level
        int M = B * n;
        int N = 5 * H;

        // gates = src_h(viewed [M, 2H]) @ Wst + b
        dim3 grid((M + BM - 1) / BM, (N + BN - 1) / BN);
        gemm_bias_split<<<grid, 256>>>(src_h, Wst, bg, gates, gates,
                                       M, N, twoH, N);

        float* ho = (lvl == levels - 1) ? (float*)d_out : dst_h;
        int total = M * H;
        lstm_cell_kernel<<<(total + 255) / 256, 256>>>(gates, src_c, ho, dst_c, M);

        // swap
        float* th = src_h; src_h = dst_h; dst_h = th;
        float* tc = src_c; src_c = dst_c; dst_c = tc;
    }
}

// round 3
// speedup vs baseline: 1.9256x; 1.9256x over previous
#include <cuda_runtime.h>
#include <cuda_bf16.h>
#include <math.h>
#include <stdint.h>

// ---------------------------------------------------------------------------
// TreeLSTM on GB300 via mma.sync bf16x3 (tcgen05 is feature-gated off by the
// harness's compute_103 PTX target — confirmed by R2 ptxas errors).
//   leaf:   hc = x[32768,300] @ W_leaf[300,256] + b_leaf   -> h | c
//   level:  gates = h_pairs[M,256] @ Wst[256,640] + b      -> cell -> h, c
// D = A_hi*B_hi + A_hi*B_lo + A_lo*B_hi, fp32 register accumulators.
// ---------------------------------------------------------------------------

#define Hc    128
#define MAXBL 32768
#define NGATE 640
#define KB_LEAF 320           // leaf K=300 padded to 320 (B side zero-filled)

__device__ float g_hA[MAXBL * Hc];
__device__ float g_cA[MAXBL * Hc];
__device__ float g_hB[(MAXBL / 2) * Hc];
__device__ float g_cB[(MAXBL / 2) * Hc];
__device__ float g_gates[(MAXBL / 2) * NGATE];
__device__ __align__(128) __nv_bfloat16 g_Wt_hi[NGATE * 256];    // [640,256]
__device__ __align__(128) __nv_bfloat16 g_Wt_lo[NGATE * 256];
__device__ __align__(128) __nv_bfloat16 g_WlfT_hi[256 * KB_LEAF]; // [256,320]
__device__ __align__(128) __nv_bfloat16 g_WlfT_lo[256 * KB_LEAF];

// ------------------------------- helpers -----------------------------------
__device__ __forceinline__ uint32_t smem_u32(const void* p) {
    uint32_t a;
    asm("{ .reg .u64 t; cvta.to.shared.u64 t, %1; cvt.u32.u64 %0, t; }"
        : "=r"(a) : "l"(p));
    return a;
}

#define CP_ASYNC16(dst, src) \
    asm volatile("cp.async.cg.shared.global [%0], [%1], 16;" \
                 :: "r"(dst), "l"(src) : "memory")
#define CP_COMMIT() asm volatile("cp.async.commit_group;" ::: "memory")
#define CP_WAIT1()  asm volatile("cp.async.wait_group 1;"  ::: "memory")

#define MMA16816(c, a, b)                                                      \
    asm volatile("mma.sync.aligned.m16n8k16.row.col.f32.bf16.bf16.f32 "       \
        "{%0,%1,%2,%3},{%4,%5,%6,%7},{%8,%9},{%0,%1,%2,%3};"                  \
        : "+f"((c)[0]), "+f"((c)[1]), "+f"((c)[2]), "+f"((c)[3])              \
        : "r"((a)[0]), "r"((a)[1]), "r"((a)[2]), "r"((a)[3]),                 \
          "r"((b)[0]), "r"((b)[1]))

__device__ __forceinline__ void split_bf16(float w, __nv_bfloat16* hi, __nv_bfloat16* lo) {
    __nv_bfloat16 h = __float2bfloat16(w);
    *hi = h;
    *lo = __float2bfloat16(w - __bfloat162float(h));
}
__device__ __forceinline__ uint32_t pack_bf(__nv_bfloat16 a, __nv_bfloat16 b) {
    __nv_bfloat162 t{a, b};
    return *(uint32_t*)&t;
}

// ------------------------ weight prep (once/replay) ------------------------
__global__ void prep_wst(const float* __restrict__ Wl, const float* __restrict__ Wr,
                         __nv_bfloat16* __restrict__ hi, __nv_bfloat16* __restrict__ lo)
{
    int idx = blockIdx.x * blockDim.x + threadIdx.x;
    if (idx >= NGATE * 256) return;
    int n = idx >> 8, k = idx & 255;
    float w = (k < 128) ? Wl[k * NGATE + n] : Wr[(k - 128) * NGATE + n];
    split_bf16(w, &hi[idx], &lo[idx]);
}

__global__ void prep_wleaf(const float* __restrict__ W,
                           __nv_bfloat16* __restrict__ hi, __nv_bfloat16* __restrict__ lo)
{
    int idx = blockIdx.x * blockDim.x + threadIdx.x;
    if (idx >= 256 * KB_LEAF) return;
    int n = idx / KB_LEAF, k = idx % KB_LEAF;
    float w = (k < 300) ? W[k * 256 + n] : 0.0f;
    split_bf16(w, &hi[idx], &lo[idx]);
}

// --------------------------- mma.sync GEMM kernel ---------------------------
// C[M, ntiles*128] = A[M,K](fp32) @ B^T + bias, B as [N,KB] bf16 hi/lo.
// CTA tile 128x128, 8 warps (2M x 4N), warp tile 64x32, BK=32 double-buffered.
// Smem per stage: A hi/lo + B hi/lo, each 128 rows x stride 40 bf16 (80B).
#define ST_ROW   80                         // bytes per smem row (40 bf16)
#define MAT_B    10240                      // 128 * 80
#define STAGE_B  (4 * MAT_B)                // 40960
#define SMEM_REQ (2 * STAGE_B)              // 81920

__global__ void __launch_bounds__(256, 1)
gemm_mma(const float* __restrict__ A,
         const __nv_bfloat16* __restrict__ Bhi, const __nv_bfloat16* __restrict__ Blo,
         const float* __restrict__ bias,
         float* __restrict__ C0, float* __restrict__ C1,
         int M, int K, int KB, int tilesplit)
{
    extern __shared__ char smem[];
    const uint32_t sbase = smem_u32(smem);

    const int tid = threadIdx.x;
    const int wid = tid >> 5, lid = tid & 31;
    const int wm = wid >> 2, wn = wid & 3;          // 2 x 4 warp grid
    const int g = lid >> 2, t2 = (lid & 3) << 1;
    const int bm = blockIdx.x * 128;
    const int ny = blockIdx.y;
    const int Kc = KB >> 5;

    float acc[4][4][4];
    #pragma unroll
    for (int i = 0; i < 4; i++)
        #pragma unroll
        for (int j = 0; j < 4; j++)
            #pragma unroll
            for (int q = 0; q < 4; q++) acc[i][j][q] = 0.f;

    float4 aReg[4];

    // --- B tile loads via cp.async: 2 matrices x 512 x 16B per stage ---
    auto issueB = [&](int ch, int s) {
        #pragma unroll
        for (int i = 0; i < 4; i++) {
            int e   = tid + i * 256;
            int mat = e >> 9;                 // 0 = hi, 1 = lo
            int rem = e & 511;
            int row = rem >> 2, cq = rem & 3;
            const __nv_bfloat16* srcm = mat ? Blo : Bhi;
            const __nv_bfloat16* src  = srcm + (size_t)(ny * 128 + row) * KB
                                             + ch * 32 + cq * 8;
            uint32_t dst = sbase + s * STAGE_B + (2 + mat) * MAT_B
                         + row * ST_ROW + cq * 16;
            CP_ASYNC16(dst, src);
        }
    };
    // --- A tile: global fp32 -> regs ---
    auto ldA = [&](int ch) {
        #pragma unroll
        for (int i = 0; i < 4; i++) {
            int e = tid + i * 256;
            int row = e >> 3, kq = e & 7;
            int k = ch * 32 + kq * 4;
            float4 v = make_float4(0.f, 0.f, 0.f, 0.f);
            if (bm + row < M && k < K)
                v = *(const float4*)(A + (size_t)(bm + row) * K + k);
            aReg[i] = v;
        }
    };
    // --- regs -> split -> smem (hi at +0, lo at +MAT_B) ---
    auto stA = [&](int s) {
        char* base = smem + s * STAGE_B;
        #pragma unroll
        for (int i = 0; i < 4; i++) {
            int e = tid + i * 256;
            int row = e >> 3, kq = e & 7;
            float4 v = aReg[i];
            __nv_bfloat16 h0, l0, h1, l1, h2, l2, h3, l3;
            split_bf16(v.x, &h0, &l0); split_bf16(v.y, &h1, &l1);
            split_bf16(v.z, &h2, &l2); split_bf16(v.w, &h3, &l3);
            uint2 hv = make_uint2(pack_bf(h0, h1), pack_bf(h2, h3));
            uint2 lv = make_uint2(pack_bf(l0, l1), pack_bf(l2, l3));
            *(uint2*)(base + row * ST_ROW + kq * 8)         = hv;
            *(uint2*)(base + MAT_B + row * ST_ROW + kq * 8) = lv;
        }
    };
    // --- compute one 32-K chunk: 2 k-steps x 16 atoms x 3 products ---
    auto compute = [&](int s) {
        const char* base = smem + s * STAGE_B;
        const char* Ah = base,            *Al = base + MAT_B;
        const char* Bh = base + 2 * MAT_B, *Bl = base + 3 * MAT_B;
        #pragma unroll
        for (int kk = 0; kk < 2; kk++) {
            const int kbyte = (kk * 16 + t2) * 2;
            uint32_t ah[4][4], al[4][4], bh[4][2], bl[4][2];
            #pragma unroll
            for (int am = 0; am < 4; am++) {
                int r = wm * 64 + am * 16 + g;
                ah[am][0] = *(const uint32_t*)(Ah + r * ST_ROW + kbyte);
                ah[am][1] = *(const uint32_t*)(Ah + (r + 8) * ST_ROW + kbyte);
                ah[am][2] = *(const uint32_t*)(Ah + r * ST_ROW + kbyte + 16);
                ah[am][3] = *(const uint32_t*)(Ah + (r + 8) * ST_ROW + kbyte + 16);
                al[am][0] = *(const uint32_t*)(Al + r * ST_ROW + kbyte);
                al[am][1] = *(const uint32_t*)(Al + (r + 8) * ST_ROW + kbyte);
                al[am][2] = *(const uint32_t*)(Al + r * ST_ROW + kbyte + 16);
                al[am][3] = *(const uint32_t*)(Al + (r + 8) * ST_ROW + kbyte + 16);
            }
            #pragma unroll
            for (int an = 0; an < 4; an++) {
                int n = wn * 32 + an * 8 + g;
                bh[an][0] = *(const uint32_t*)(Bh + n * ST_ROW + kbyte);
                bh[an][1] = *(const uint32_t*)(Bh + n * ST_ROW + kbyte + 16);
                bl[an][0] = *(const uint32_t*)(Bl + n * ST_ROW + kbyte);
                bl[an][1] = *(const uint32_t*)(Bl + n * ST_ROW + kbyte + 16);
            }
            #pragma unroll
            for (int am = 0; am < 4; am++)
                #pragma unroll
                for (int an = 0; an < 4; an++) {
                    MMA16816(acc[am][an], ah[am], bh[an]);
                    MMA16816(acc[am][an], ah[am], bl[an]);
                    MMA16816(acc[am][an], al[am], bh[an]);
                }
        }
    };

    // --- pipelined mainloop ---
    issueB(0, 0); CP_COMMIT();
    ldA(0); stA(0);
    for (int ch = 0; ch < Kc; ch++) {
        const int s = ch & 1, nsg = s ^ 1;
        const bool more = (ch + 1 < Kc);
        if (more) { issueB(ch + 1, nsg); ldA(ch + 1); }
        CP_COMMIT();
        CP_WAIT1();
        __syncthreads();
        compute(s);
        if (more) stA(nsg);
    }

    // --- epilogue: regs + bias -> global (split routing) ---
    float* out; int colb, rs;
    if (ny < tilesplit) { out = C0; colb = ny * 128;               rs = tilesplit * 128; }
    else                { out = C1; colb = (ny - tilesplit) * 128; rs = ((int)gridDim.y - tilesplit) * 128; }

    #pragma unroll
    for (int am = 0; am < 4; am++) {
        int r0 = bm + wm * 64 + am * 16 + g;
        #pragma unroll
        for (int an = 0; an < 4; an++) {
            int c  = wn * 32 + an * 8 + t2;
            int gc = ny * 128 + c;
            float b0 = bias[gc], b1 = bias[gc + 1];
            if (r0 < M) {
                float2 v = make_float2(acc[am][an][0] + b0, acc[am][an][1] + b1);
                *(float2*)(out + (size_t)r0 * rs + colb + c) = v;
            }
            if (r0 + 8 < M) {
                float2 v = make_float2(acc[am][an][2] + b0, acc[am][an][3] + b1);
                *(float2*)(out + (size_t)(r0 + 8) * rs + colb + c) = v;
            }
        }
    }
}

// ------------------------------- LSTM cell ---------------------------------
__device__ __forceinline__ float sigf(float x) { return 1.0f / (1.0f + expf(-x)); }

__global__ void lstm_cell4(const float* __restrict__ gates,
                           const float* __restrict__ c_prev,
                           float* __restrict__ h_out, float* __restrict__ c_out, int M)
{
    int idx = blockIdx.x * blockDim.x + threadIdx.x;
    if (idx >= M * 32) return;
    int r = idx >> 5, j = (idx & 31) << 2;
    const float* g = gates + (size_t)r * NGATE;
    float4 i4  = *(const float4*)(g + j);
    float4 fl4 = *(const float4*)(g + 128 + j);
    float4 fr4 = *(const float4*)(g + 256 + j);
    float4 o4  = *(const float4*)(g + 384 + j);
    float4 g4  = *(const float4*)(g + 512 + j);
    const float* cp = c_prev + (size_t)r * 256;
    float4 cl4 = *(const float4*)(cp + j);
    float4 cr4 = *(const float4*)(cp + 128 + j);
    float4 c, h;
#define CEL(X) { float ii = sigf(i4.X), fl = sigf(fl4.X), fr = sigf(fr4.X);      \
                 float oo = sigf(o4.X), gg = tanhf(g4.X);                        \
                 float cc = fl * cl4.X + fr * cr4.X + ii * gg;                   \
                 c.X = cc; h.X = oo * tanhf(cc); }
    CEL(x) CEL(y) CEL(z) CEL(w)
#undef CEL
    *(float4*)(c_out + (size_t)r * Hc + j) = c;
    *(float4*)(h_out + (size_t)r * Hc + j) = h;
}

// --------------------------------- launch ----------------------------------
extern "C" void kernel_launch(void* const* d_in, const int* in_sizes, int n_in,
                              void* d_out, int out_size)
{
    const float* x      = (const float*)d_in[0];
    const float* W_leaf = (const float*)d_in[1];
    const float* b_leaf = (const float*)d_in[2];
    const float* W_l    = (const float*)d_in[3];
    const float* W_r    = (const float*)d_in[4];
    const float* bg     = (const float*)d_in[5];

    const int twoH = in_sizes[2];            // 256
    const int H    = twoH / 2;               // 128
    const int D    = in_sizes[1] / twoH;     // 300
    const int BL   = in_sizes[0] / D;        // 32768
    const int B    = out_size / H;           // 8
    const int L    = BL / B;                 // 4096
    int levels = 0;
    for (int t = L; t > 1; t >>= 1) levels++;

    float *hA, *cA, *hB, *cB, *gates;
    __nv_bfloat16 *Wt_hi, *Wt_lo, *Wlf_hi, *Wlf_lo;
    cudaGetSymbolAddress((void**)&hA,     g_hA);
    cudaGetSymbolAddress((void**)&cA,     g_cA);
    cudaGetSymbolAddress((void**)&hB,     g_hB);
    cudaGetSymbolAddress((void**)&cB,     g_cB);
    cudaGetSymbolAddress((void**)&gates,  g_gates);
    cudaGetSymbolAddress((void**)&Wt_hi,  g_Wt_hi);
    cudaGetSymbolAddress((void**)&Wt_lo,  g_Wt_lo);
    cudaGetSymbolAddress((void**)&Wlf_hi, g_WlfT_hi);
    cudaGetSymbolAddress((void**)&Wlf_lo, g_WlfT_lo);

    cudaFuncSetAttribute(gemm_mma, cudaFuncAttributeMaxDynamicSharedMemorySize, SMEM_REQ);

    // 1) weight prep
    prep_wst  <<<(NGATE * 256 + 255) / 256, 256>>>(W_l, W_r, Wt_hi, Wt_lo);
    prep_wleaf<<<(256 * KB_LEAF + 255) / 256, 256>>>(W_leaf, Wlf_hi, Wlf_lo);

    // 2) leaf GEMM -> h | c
    {
        dim3 grid((BL + 127) / 128, 2);
        gemm_mma<<<grid, 256, SMEM_REQ>>>(x, Wlf_hi, Wlf_lo, b_leaf,
                                          hA, cA, BL, D, KB_LEAF, 1);
    }

    // 3) reduction levels
    float* src_h = hA; float* src_c = cA;
    float* dst_h = hB; float* dst_c = cB;
    int n = L;
    for (int lvl = 0; lvl < levels; lvl++) {
        n >>= 1;
        int M = B * n;

        dim3 grid((M + 127) / 128, 5);
        gemm_mma<<<grid, 256, SMEM_REQ>>>(src_h, Wt_hi, Wt_lo, bg,
                                          gates, gates, M, twoH, twoH, 5);

        float* ho = (lvl == levels - 1) ? (float*)d_out : dst_h;
        lstm_cell4<<<(M * 32 + 255) / 256, 256>>>(gates, src_c, ho, dst_c, M);

        float* th = src_h; src_h = dst_h; dst_h = th;
        float* tc = src_c; src_c = dst_c; dst_c = tc;
    }
}